// round 4
// baseline (speedup 1.0000x reference)
#include <cuda_runtime.h>

// ---------------- problem constants ----------------
#define N_ATOMS     20000
#define N_EDGES     640000
#define N_ANG_EDGES 160000
#define N_PAIRS     560000
#define N_FEAT      407        // 87 onehot + 64 radial + 256 angular

// ---------------- device scratch (allocation-free rule) ----------------
__device__ __align__(16) float g_val   [N_ATOMS * 4];
__device__ __align__(16) float g_edge  [N_ANG_EDGES * 8];   // {d, sw, v0..v3, pad, pad}
__device__ int   g_cnt_r [N_ATOMS];
__device__ int   g_off_r [N_ATOMS + 1];
__device__ int   g_cur_r [N_ATOMS];
__device__ int   g_cnt_a [N_ATOMS];
__device__ int   g_off_a [N_ATOMS + 1];
__device__ int   g_cur_a [N_ATOMS];
__device__ __align__(16) float g_pay_r[N_EDGES * 8];        // {d, s, v0..v3, pad, pad}
__device__ __align__(16) float g_pay_a[N_PAIRS * 16];       // {f1[4], f2sw[4], vp[4], vm[4]}

// ---------------- kernels ----------------

__global__ void k_zero() {
    int idx = blockIdx.x * blockDim.x + threadIdx.x;
    int stride = gridDim.x * blockDim.x;
    for (int i = idx; i < N_ATOMS; i += stride) { g_cnt_r[i] = 0; g_cnt_a[i] = 0; }
}

// valence gather + angular-edge struct build + both histograms
__global__ void k_prep(const int* __restrict__ species,
                       const float* __restrict__ vtab,
                       const int* __restrict__ ang_dst,
                       const float* __restrict__ ang_d,
                       const float* __restrict__ ang_sw,
                       const int* __restrict__ catom,
                       const int* __restrict__ esrc) {
    int idx = blockIdx.x * blockDim.x + threadIdx.x;
    int stride = gridDim.x * blockDim.x;
    for (int t = idx; t < N_ATOMS; t += stride) {
        int sp = species[t];
        ((float4*)g_val)[t] = *(const float4*)(vtab + sp * 4);
    }
    for (int t = idx; t < N_ANG_EDGES; t += stride) {
        int dst = ang_dst[t];
        int sp  = species[dst];
        float4 v = *(const float4*)(vtab + sp * 4);
        ((float4*)g_edge)[t * 2 + 0] = make_float4(ang_d[t], ang_sw[t], v.x, v.y);
        ((float4*)g_edge)[t * 2 + 1] = make_float4(v.z, v.w, 0.f, 0.f);
    }
    for (int t = idx; t < N_PAIRS; t += stride) atomicAdd(&g_cnt_a[catom[t]], 1);
    for (int t = idx; t < N_EDGES; t += stride) atomicAdd(&g_cnt_r[esrc[t]], 1);
}

// two-block exclusive scan: block 0 -> radial counts, block 1 -> angular counts
__global__ void k_scan() {
    const int CHUNK = 20;                 // 1024 * 20 = 20480 >= N_ATOMS
    __shared__ int warp_sums[32];
    const int* cnt = (blockIdx.x == 0) ? g_cnt_r : g_cnt_a;
    int* off       = (blockIdx.x == 0) ? g_off_r : g_off_a;
    int* cur       = (blockIdx.x == 0) ? g_cur_r : g_cur_a;

    int t = threadIdx.x;
    int base = t * CHUNK;
    int local[CHUNK];
    int sum = 0;
    #pragma unroll
    for (int u = 0; u < CHUNK; u++) {
        int i = base + u;
        int v = (i < N_ATOMS) ? cnt[i] : 0;
        local[u] = sum;
        sum += v;
    }
    int lane = t & 31, wid = t >> 5;
    int incl = sum;
    #pragma unroll
    for (int offt = 1; offt < 32; offt <<= 1) {
        int x = __shfl_up_sync(0xFFFFFFFFu, incl, offt);
        if (lane >= offt) incl += x;
    }
    if (lane == 31) warp_sums[wid] = incl;
    __syncthreads();
    if (wid == 0) {
        int w = warp_sums[lane];
        #pragma unroll
        for (int offt = 1; offt < 32; offt <<= 1) {
            int x = __shfl_up_sync(0xFFFFFFFFu, w, offt);
            if (lane >= offt) w += x;
        }
        warp_sums[lane] = w;
    }
    __syncthreads();
    int excl_base = incl - sum + (wid > 0 ? warp_sums[wid - 1] : 0);
    #pragma unroll
    for (int u = 0; u < CHUNK; u++) {
        int i = base + u;
        if (i < N_ATOMS) {
            int e = excl_base + local[u];
            off[i] = e;
            cur[i] = e;
        }
    }
    if (t == 1023) off[N_ATOMS] = excl_base + sum;
}

// fused scatter: radial edges -> 32B payload, angular pairs -> 64B payload
__global__ void k_scatter(const float* __restrict__ dist,
                          const float* __restrict__ swc,
                          const int* __restrict__ esrc,
                          const int* __restrict__ edst,
                          const float* __restrict__ angles,
                          const int* __restrict__ pasrc,
                          const int* __restrict__ padst,
                          const int* __restrict__ catom) {
    int idx = blockIdx.x * blockDim.x + threadIdx.x;
    int stride = gridDim.x * blockDim.x;

    // ---- radial edges ----
    for (int e = idx; e < N_EDGES; e += stride) {
        float d = dist[e];
        float s = 0.25f * swc[e];
        int a   = esrc[e];
        float4 v = ((const float4*)g_val)[edst[e]];
        int pos = atomicAdd(&g_cur_r[a], 1);
        float4* P = (float4*)(g_pay_r + pos * 8);
        P[0] = make_float4(d, s, v.x, v.y);
        P[1] = make_float4(v.z, v.w, 0.f, 0.f);
    }

    // ---- angular pairs ----
    for (int p = idx; p < N_PAIRS; p += stride) {
        int ea = pasrc[p];
        int eb = padst[p];
        float4 A0 = ((const float4*)g_edge)[ea * 2 + 0];
        float4 A1 = ((const float4*)g_edge)[ea * 2 + 1];
        float4 B0 = ((const float4*)g_edge)[eb * 2 + 0];
        float4 B1 = ((const float4*)g_edge)[eb * 2 + 1];

        float d12 = 0.5f * (A0.x + B0.x);
        float swp = 2.0f * A0.y * B0.y;

        float sn, cs;
        __sincosf(angles[p], &sn, &cs);
        const float CZ[4] = { 0.92387953f,  0.38268343f, -0.38268343f, -0.92387953f};
        const float SZ[4] = { 0.38268343f,  0.92387953f,  0.92387953f,  0.38268343f};
        float f1[4];
        #pragma unroll
        for (int k = 0; k < 4; k++) {
            float u = 0.5f + 0.5f * (cs * CZ[k] + sn * SZ[k]);
            float u2 = u * u, u4 = u2 * u2, u8 = u4 * u4, u16 = u8 * u8;
            f1[k] = u16 * u16;
        }
        float f2[4];
        #pragma unroll
        for (int a = 0; a < 4; a++) {
            float x = d12 - (0.8f + 0.675f * (float)a);
            f2[a] = swp * __expf(-8.0f * x * x);
        }

        int c = catom[p];
        int pos = atomicAdd(&g_cur_a[c], 1);
        float4* P = (float4*)(g_pay_a + pos * 16);
        P[0] = make_float4(f1[0], f1[1], f1[2], f1[3]);
        P[1] = make_float4(f2[0], f2[1], f2[2], f2[3]);
        P[2] = make_float4(A0.z + B0.z, A0.w + B0.w, A1.x + B1.x, A1.y + B1.y);
        P[3] = make_float4(A0.z * B0.z, A0.w * B0.w, A1.x * B1.x, A1.y * B1.y);
    }
}

// warp-per-atom: onehot (cols 0..86) + radial (cols 87..150), no atomics.
// radial col 87 + j*4 + i ; lane -> (j = lane>>2, i = lane&3) covers cols 87+lane
// and 87+32+lane (j and j+8).
__global__ void k_rad_gather(const int* __restrict__ species,
                             float* __restrict__ out) {
    int gw = (blockIdx.x * blockDim.x + threadIdx.x) >> 5;
    if (gw >= N_ATOMS) return;
    int lane = threadIdx.x & 31;

    float* o = out + (size_t)gw * N_FEAT;
    int sp = species[gw];
    #pragma unroll
    for (int c = lane; c < 87; c += 32) o[c] = (c == sp) ? 1.0f : 0.0f;

    int i = lane & 3;
    int jb = lane >> 2;
    float sh1 = 0.8f + 0.275f * (float)jb;
    float sh2 = 0.8f + 0.275f * (float)(jb + 8);

    int start = g_off_r[gw];
    int end   = g_off_r[gw + 1];
    float acc0 = 0.f, acc1 = 0.f;
    for (int p = start; p < end; p++) {
        const float* P = g_pay_r + p * 8;
        float d = P[0];
        float s = P[1];
        float vi = P[2 + i];
        float x1 = d - sh1, x2 = d - sh2;
        float t1 = s * __expf(-16.0f * x1 * x1);
        float t2 = s * __expf(-16.0f * x2 * x2);
        acc0 = fmaf(t1, vi, acc0);
        acc1 = fmaf(t2, vi, acc1);
    }
    o[87 + lane]      = acc0;
    o[87 + 32 + lane] = acc1;
}

// warp-per-atom angular gather -> cols 151..406
__global__ void k_ang_gather(float* __restrict__ out) {
    int gw = (blockIdx.x * blockDim.x + threadIdx.x) >> 5;
    if (gw >= N_ATOMS) return;
    int lane = threadIdx.x & 31;
    int hi = lane >> 4;
    int i  = (lane & 15) >> 2;
    int j  = lane & 3;

    int start = g_off_a[gw];
    int end   = g_off_a[gw + 1];

    float acc[8];
    #pragma unroll
    for (int r = 0; r < 8; r++) acc[r] = 0.f;

    for (int p = start; p < end; p++) {
        const float4* P = (const float4*)(g_pay_a + p * 16);
        float4 F1 = P[0];
        float4 F2 = P[1];
        float vp = ((const float*)(P + 2))[i];
        float vm = ((const float*)(P + 3))[j];
        float wv = vp * vm;
        float f1e = hi ? F1.y : F1.x;       // k = hi      (even r)
        float f1o = hi ? F1.w : F1.z;       // k = 2 + hi  (odd r)
        float we = wv * f1e;
        float wo = wv * f1o;
        acc[0] = fmaf(we, F2.x, acc[0]);  acc[1] = fmaf(wo, F2.x, acc[1]);
        acc[2] = fmaf(we, F2.y, acc[2]);  acc[3] = fmaf(wo, F2.y, acc[3]);
        acc[4] = fmaf(we, F2.z, acc[4]);  acc[5] = fmaf(wo, F2.z, acc[5]);
        acc[6] = fmaf(we, F2.w, acc[6]);  acc[7] = fmaf(wo, F2.w, acc[7]);
    }

    float* o = out + (size_t)gw * N_FEAT + 151;
    #pragma unroll
    for (int r = 0; r < 8; r++) o[r * 32 + lane] = acc[r];
}

// ---------------- launcher ----------------
extern "C" void kernel_launch(void* const* d_in, const int* in_sizes, int n_in,
                              void* d_out, int out_size) {
    const int*   species = (const int*)  d_in[0];
    const float* dist    = (const float*)d_in[1];
    const float* swch    = (const float*)d_in[2];
    const int*   esrc    = (const int*)  d_in[3];
    const int*   edst    = (const int*)  d_in[4];
    const float* ang     = (const float*)d_in[5];
    const float* adist   = (const float*)d_in[6];
    const float* asw     = (const float*)d_in[7];
    const int*   aedst   = (const int*)  d_in[8];
    const int*   pasrc   = (const int*)  d_in[9];
    const int*   padst   = (const int*)  d_in[10];
    const int*   catom   = (const int*)  d_in[11];
    const float* vtab    = (const float*)d_in[12];
    float* out = (float*)d_out;

    k_zero<<<80, 256>>>();
    k_prep<<<1280, 256>>>(species, vtab, aedst, adist, asw, catom, esrc);
    k_scan<<<2, 1024>>>();
    k_scatter<<<2500, 256>>>(dist, swch, esrc, edst, ang, pasrc, padst, catom);
    k_rad_gather<<<2500, 256>>>(species, out);
    k_ang_gather<<<2500, 256>>>(out);
}